// round 1
// baseline (speedup 1.0000x reference)
#include <cuda_runtime.h>
#include <math.h>

// ---------------------------------------------------------------------------
// NNLS PGD step:
//   new_X = relu(th1 @ Y + weight)
//   Y_new = new_X + (k-1)/(k+2) * (new_X - X_old)
// Output layout (float32): [ Y_new (K*B) | new_X (K*B) | k+1 (1) | weight (K*B) ]
// ---------------------------------------------------------------------------

constexpr int BM = 128;
constexpr int BN = 128;
constexpr int BK = 16;
constexpr int TM = 8;
constexpr int TN = 8;
// threads = (BM/TM)*(BN/TN) = 256

__global__ __launch_bounds__(256, 2)
void nnls_fused_gemm(const float* __restrict__ A,    // th1 [K,K] row-major
                     const float* __restrict__ B,    // Y   [K,N] row-major
                     const float* __restrict__ Xold, // [K,N]
                     const float* __restrict__ W,    // [K,N]
                     const int*   __restrict__ kptr, // scalar
                     float*       __restrict__ out,  // Y_new at 0, new_X at K*N
                     int K, int N)
{
    __shared__ float As[BK][BM];  // A tile stored transposed
    __shared__ float Bs[BK][BN];

    const int tid  = threadIdx.x;
    const int tr   = tid >> 4;          // 0..15  (row group)
    const int tc   = tid & 15;          // 0..15  (col group)
    const int row0 = blockIdx.y * BM;
    const int col0 = blockIdx.x * BN;

    // A-tile load mapping: 128x16 floats = 512 float4, 2 per thread
    const int a_row  = tid >> 2;            // 0..63
    const int a_col4 = (tid & 3) << 2;      // 0,4,8,12
    // B-tile load mapping: 16x128 floats = 512 float4, 2 per thread
    const int b_row  = tid >> 5;            // 0..7
    const int b_col4 = (tid & 31) << 2;     // 0..124

    float acc[TM][TN] = {};

    for (int k0 = 0; k0 < K; k0 += BK) {
        #pragma unroll
        for (int i = 0; i < 2; i++) {
            const int r = a_row + i * 64;
            float4 v = *reinterpret_cast<const float4*>(
                &A[(long long)(row0 + r) * K + k0 + a_col4]);
            As[a_col4 + 0][r] = v.x;
            As[a_col4 + 1][r] = v.y;
            As[a_col4 + 2][r] = v.z;
            As[a_col4 + 3][r] = v.w;
        }
        #pragma unroll
        for (int i = 0; i < 2; i++) {
            const int r = b_row + i * 8;
            float4 v = *reinterpret_cast<const float4*>(
                &B[(long long)(k0 + r) * N + col0 + b_col4]);
            *reinterpret_cast<float4*>(&Bs[r][b_col4]) = v;
        }
        __syncthreads();

        #pragma unroll
        for (int kk = 0; kk < BK; kk++) {
            float ar[TM], br[TN];
            #pragma unroll
            for (int m = 0; m < TM; m++) ar[m] = As[kk][tr * TM + m];
            #pragma unroll
            for (int n = 0; n < TN; n++) br[n] = Bs[kk][tc * TN + n];
            #pragma unroll
            for (int m = 0; m < TM; m++)
                #pragma unroll
                for (int n = 0; n < TN; n++)
                    acc[m][n] = fmaf(ar[m], br[n], acc[m][n]);
        }
        __syncthreads();
    }

    // Fused epilogue
    const float kf  = (float)kptr[0];
    const float mom = (kf - 1.0f) / (kf + 2.0f);
    const long long nTot = (long long)K * N;

    #pragma unroll
    for (int m = 0; m < TM; m++) {
        const int r = row0 + tr * TM + m;
        const long long base = (long long)r * N + col0 + tc * TN;
        #pragma unroll
        for (int n = 0; n < TN; n += 4) {
            float4 w  = *reinterpret_cast<const float4*>(&W[base + n]);
            float4 xo = *reinterpret_cast<const float4*>(&Xold[base + n]);
            float4 nx, yn;
            nx.x = fmaxf(acc[m][n + 0] + w.x, 0.0f);
            nx.y = fmaxf(acc[m][n + 1] + w.y, 0.0f);
            nx.z = fmaxf(acc[m][n + 2] + w.z, 0.0f);
            nx.w = fmaxf(acc[m][n + 3] + w.w, 0.0f);
            yn.x = nx.x + mom * (nx.x - xo.x);
            yn.y = nx.y + mom * (nx.y - xo.y);
            yn.z = nx.z + mom * (nx.z - xo.z);
            yn.w = nx.w + mom * (nx.w - xo.w);
            *reinterpret_cast<float4*>(&out[nTot + base + n]) = nx;  // new_X
            *reinterpret_cast<float4*>(&out[base + n])        = yn;  // Y_new
        }
    }
}

// Tail: out[2n] = k+1 ; out[2n+1 .. 2n+n] = weight
__global__ void nnls_tail(const float* __restrict__ W,
                          const int*   __restrict__ kptr,
                          float*       __restrict__ out,
                          long long n)
{
    long long i = (long long)blockIdx.x * blockDim.x + threadIdx.x;
    const long long stride = (long long)gridDim.x * blockDim.x;
    if (i == 0) out[2 * n] = (float)(kptr[0] + 1);
    for (; i < n; i += stride)
        out[2 * n + 1 + i] = W[i];
}

extern "C" void kernel_launch(void* const* d_in, const int* in_sizes, int n_in,
                              void* d_out, int out_size)
{
    const float* th1  = (const float*)d_in[0];
    const float* Y    = (const float*)d_in[1];
    const float* Xold = (const float*)d_in[2];
    const int*   kptr = (const int*)  d_in[3];
    const float* W    = (const float*)d_in[4];
    float* out = (float*)d_out;

    // K from th1 (K*K elements), N from Y (K*N elements)
    int K = (int)lround(sqrt((double)in_sizes[0]));
    int N = in_sizes[1] / K;

    dim3 grid(N / BN, K / BM);
    nnls_fused_gemm<<<grid, 256>>>(th1, Y, Xold, W, kptr, out, K, N);

    const long long n = (long long)K * N;
    nnls_tail<<<1024, 256>>>(W, kptr, out, n);
}

// round 3
// speedup vs baseline: 2.1857x; 2.1857x over previous
#include <cuda_runtime.h>
#include <cstdint>
#include <math.h>

// ---------------------------------------------------------------------------
// NNLS PGD step via tf32 mma.sync (legal on compute_103 virtual arch):
//   D     = (th1 - I) @ Y          (tf32 tensor cores, tiny operands => tiny error)
//   new_X = relu(D + Y + weight)   (exact fp32 identity term)
//   Y_new = new_X + (k-1)/(k+2) * (new_X - X_old)
// out: [ Y_new (K*B) | new_X (K*B) | k+1 (1) | weight (K*B) ]
// ---------------------------------------------------------------------------

#define BM 128
#define BN 128
#define BK 16
#define THREADS 256

#define A_PITCH 20    // floats per A smem row  (bank-conflict-free frag loads)
#define B_PITCH 136   // floats per B smem row

__shared__ float As_s[2][BM][A_PITCH];
__shared__ float Bs_s[2][BK][B_PITCH];

#define CP_ASYNC16(dst_u32, src_ptr) \
    asm volatile("cp.async.cg.shared.global [%0], [%1], 16;" :: "r"(dst_u32), "l"(src_ptr))
#define CP_COMMIT() asm volatile("cp.async.commit_group;")
#define CP_WAIT1()  asm volatile("cp.async.wait_group 1;")
#define CP_WAIT0()  asm volatile("cp.async.wait_group 0;")

#define MMA_TF32(c, a, b) \
    asm volatile("mma.sync.aligned.m16n8k8.row.col.f32.tf32.tf32.f32 " \
        "{%0,%1,%2,%3}, {%4,%5,%6,%7}, {%8,%9}, {%0,%1,%2,%3};" \
        : "+f"((c)[0]), "+f"((c)[1]), "+f"((c)[2]), "+f"((c)[3]) \
        : "r"((a)[0]), "r"((a)[1]), "r"((a)[2]), "r"((a)[3]), \
          "r"((b)[0]), "r"((b)[1]))

__global__ __launch_bounds__(THREADS)
void nnls_mma_kernel(const float* __restrict__ A,    // th1 [Kd,Kd]
                     const float* __restrict__ Y,    // [Kd,N]
                     const float* __restrict__ Xold, // [Kd,N]
                     const int*   __restrict__ kptr,
                     const float* __restrict__ W,    // [Kd,N]
                     float*       __restrict__ out,
                     int Kd, int N)
{
    const int tid    = threadIdx.x;
    const int wid    = tid >> 5;
    const int lane   = tid & 31;
    const int lr     = lane >> 2;     // 0..7
    const int lq     = lane & 3;      // 0..3
    const int warp_m = wid & 3;       // 4 warps along M (32 rows each)
    const int warp_n = wid >> 2;      // 2 warps along N (64 cols each)
    const int m0     = blockIdx.x * BM;   // x = m so consecutive CTAs share B tile
    const int n0     = blockIdx.y * BN;
    const int NS     = Kd / BK;

    // A load mapping: 128 rows x 4 float4 per tile = 512 f4, 2 per thread
    const int am  = tid >> 1;                 // wrong granularity? no: idx-based below
    (void)am;

    // B cp.async mapping: 16 rows x 32 float4 = 512 f4, 2 per thread
    float4 ra[2];

    // ---- helpers as lambdas ----
    auto loadA = [&](int k0, float4* r) {
        #pragma unroll
        for (int i = 0; i < 2; i++) {
            int idx = tid + THREADS * i;
            int arow = idx >> 2, ak4 = idx & 3;
            float4 v = *reinterpret_cast<const float4*>(
                &A[(long long)(m0 + arow) * Kd + k0 + ak4 * 4]);
            // subtract identity in fp32 BEFORE tf32 truncation
            int grow = m0 + arow;
            int gk   = k0 + ak4 * 4;
            if (grow == gk + 0) v.x -= 1.0f;
            if (grow == gk + 1) v.y -= 1.0f;
            if (grow == gk + 2) v.z -= 1.0f;
            if (grow == gk + 3) v.w -= 1.0f;
            r[i] = v;
        }
    };
    auto stsA = [&](int buf, const float4* r) {
        #pragma unroll
        for (int i = 0; i < 2; i++) {
            int idx = tid + THREADS * i;
            int arow = idx >> 2, ak4 = idx & 3;
            *reinterpret_cast<float4*>(&As_s[buf][arow][ak4 * 4]) = r[i];
        }
    };
    auto cpB = [&](int buf, int k0) {
        #pragma unroll
        for (int i = 0; i < 2; i++) {
            int idx = tid + THREADS * i;
            int bk = idx >> 5, bn4 = idx & 31;
            uint32_t dst = (uint32_t)__cvta_generic_to_shared(&Bs_s[buf][bk][bn4 * 4]);
            const float* src = &Y[(long long)(k0 + bk) * N + n0 + bn4 * 4];
            CP_ASYNC16(dst, src);
        }
        CP_COMMIT();
    };

    float acc[2][8][4] = {};

    // ---- prologue ----
    loadA(0, ra);
    cpB(0, 0);

    for (int s = 0; s < NS; ++s) {
        const int buf = s & 1;
        stsA(buf, ra);
        if (s + 1 < NS) {
            cpB(buf ^ 1, (s + 1) * BK);
            loadA((s + 1) * BK, ra);
            CP_WAIT1();
        } else {
            CP_WAIT0();
        }
        __syncthreads();

        const float (*a_t)[A_PITCH] = As_s[buf];
        const float (*b_t)[B_PITCH] = Bs_s[buf];

        #pragma unroll
        for (int kk = 0; kk < 2; kk++) {
            const int kb = kk * 8;
            uint32_t bfr[8][2], afr[2][4];
            #pragma unroll
            for (int nt = 0; nt < 8; nt++) {
                int col = warp_n * 64 + nt * 8 + lr;
                bfr[nt][0] = __float_as_uint(b_t[kb + lq][col]);
                bfr[nt][1] = __float_as_uint(b_t[kb + lq + 4][col]);
            }
            #pragma unroll
            for (int mt = 0; mt < 2; mt++) {
                int row = warp_m * 32 + mt * 16 + lr;
                afr[mt][0] = __float_as_uint(a_t[row][kb + lq]);
                afr[mt][1] = __float_as_uint(a_t[row + 8][kb + lq]);
                afr[mt][2] = __float_as_uint(a_t[row][kb + lq + 4]);
                afr[mt][3] = __float_as_uint(a_t[row + 8][kb + lq + 4]);
            }
            #pragma unroll
            for (int mt = 0; mt < 2; mt++)
                #pragma unroll
                for (int nt = 0; nt < 8; nt++)
                    MMA_TF32(acc[mt][nt], afr[mt], bfr[nt]);
        }
        __syncthreads();
    }

    // ---------------- fused epilogue ----------------
    const long long KN = (long long)Kd * N;
    const float kf  = (float)kptr[0];
    const float mom = (kf - 1.0f) / (kf + 2.0f);

    #pragma unroll
    for (int mt = 0; mt < 2; mt++) {
        #pragma unroll
        for (int i = 0; i < 2; i++) {
            const int row = m0 + warp_m * 32 + mt * 16 + lr + i * 8;
            #pragma unroll
            for (int nt = 0; nt < 8; nt++) {
                const int col = n0 + warp_n * 64 + nt * 8 + lq * 2;
                const long long gi = (long long)row * N + col;
                float2 y2  = *reinterpret_cast<const float2*>(&Y[gi]);
                float2 w2  = *reinterpret_cast<const float2*>(&W[gi]);
                float2 xo2 = *reinterpret_cast<const float2*>(&Xold[gi]);
                float d0 = acc[mt][nt][i * 2 + 0] + y2.x + w2.x;
                float d1 = acc[mt][nt][i * 2 + 1] + y2.y + w2.y;
                float nx0 = fmaxf(d0, 0.0f);
                float nx1 = fmaxf(d1, 0.0f);
                float2 yn, nx;
                nx.x = nx0; nx.y = nx1;
                yn.x = nx0 + mom * (nx0 - xo2.x);
                yn.y = nx1 + mom * (nx1 - xo2.y);
                *reinterpret_cast<float2*>(&out[gi])      = yn;  // Y_new
                *reinterpret_cast<float2*>(&out[KN + gi]) = nx;  // new_X
                out[2 * KN + 1 + gi]     = w2.x;                 // weight copy
                out[2 * KN + 1 + gi + 1] = w2.y;
            }
        }
    }
    if (m0 == 0 && n0 == 0 && tid == 0) out[2 * KN] = kf + 1.0f;
}

extern "C" void kernel_launch(void* const* d_in, const int* in_sizes, int n_in,
                              void* d_out, int out_size)
{
    const float* th1  = (const float*)d_in[0];
    const float* Y    = (const float*)d_in[1];
    const float* Xold = (const float*)d_in[2];
    const int*   kptr = (const int*)  d_in[3];
    const float* W    = (const float*)d_in[4];
    float* out = (float*)d_out;

    int Kd = (int)lround(sqrt((double)in_sizes[0]));
    int N  = in_sizes[1] / Kd;

    dim3 grid(Kd / BM, N / BN);   // (8, 64)
    nnls_mma_kernel<<<grid, THREADS>>>(th1, Y, Xold, kptr, W, out, Kd, N);
}

// round 5
// speedup vs baseline: 2.8049x; 1.2833x over previous
#include <cuda_runtime.h>
#include <cstdint>
#include <math.h>

// ---------------------------------------------------------------------------
// NNLS PGD step via tf32 mma.sync, 3-stage cp.async pipeline:
//   D     = (th1 - I) @ Y          (identity subtracted in-smem on diag tiles)
//   new_X = relu(D + Y + weight)   (exact fp32 identity term re-added)
//   Y_new = new_X + (k-1)/(k+2) * (new_X - X_old)
// out: [ Y_new (K*B) | new_X (K*B) | k+1 (1) | weight (K*B) ]
// ---------------------------------------------------------------------------

#define BM 128
#define BN 128
#define BK 16
#define THREADS 256
#define STAGES 3

#define A_PITCH 20     // floats per A smem row
#define B_PITCH 136    // floats per B smem row
#define A_STAGE (BM * A_PITCH)          // 2560 floats
#define B_STAGE (BK * B_PITCH)          // 2176 floats
#define B_BASE  (STAGES * A_STAGE)      // 7680 floats
#define SMEM_FLOATS (B_BASE + STAGES * B_STAGE)   // 14208
#define SMEM_BYTES  (SMEM_FLOATS * 4)             // 56832

#define CP_ASYNC16(dst_u32, src_ptr) \
    asm volatile("cp.async.cg.shared.global [%0], [%1], 16;" :: "r"(dst_u32), "l"(src_ptr))
#define CP_COMMIT() asm volatile("cp.async.commit_group;")
#define CP_WAIT1()  asm volatile("cp.async.wait_group 1;")

#define MMA_TF32(c, a, b) \
    asm volatile("mma.sync.aligned.m16n8k8.row.col.f32.tf32.tf32.f32 " \
        "{%0,%1,%2,%3}, {%4,%5,%6,%7}, {%8,%9}, {%0,%1,%2,%3};" \
        : "+f"((c)[0]), "+f"((c)[1]), "+f"((c)[2]), "+f"((c)[3]) \
        : "r"((a)[0]), "r"((a)[1]), "r"((a)[2]), "r"((a)[3]), \
          "r"((b)[0]), "r"((b)[1]))

__global__ __launch_bounds__(THREADS, 2)
void nnls_mma_kernel(const float* __restrict__ A,    // th1 [Kd,Kd]
                     const float* __restrict__ Y,    // [Kd,N]
                     const float* __restrict__ Xold, // [Kd,N]
                     const int*   __restrict__ kptr,
                     const float* __restrict__ W,    // [Kd,N]
                     float*       __restrict__ out,
                     int Kd, int N)
{
    extern __shared__ float smem[];

    const int tid    = threadIdx.x;
    const int wid    = tid >> 5;
    const int lane   = tid & 31;
    const int lr     = lane >> 2;     // 0..7
    const int lq     = lane & 3;      // 0..3
    const int warp_m = wid & 3;       // 4 warps along M
    const int warp_n = wid >> 2;      // 2 warps along N
    const int m0     = blockIdx.x * BM;
    const int n0     = blockIdx.y * BN;
    const int NS     = Kd / BK;       // 64

    // per-thread cp.async coordinates (2 chunks each for A and B)
    const int arow0 = tid >> 2,  ac0 = tid & 3;          // + 64 rows for i=1
    const int bk0   = tid >> 5,  bn0 = tid & 31;         // + 8 rows for i=1

    const float* srcA0 = A + (long long)(m0 + arow0) * Kd + ac0 * 4;
    const float* srcA1 = srcA0 + (long long)64 * Kd;
    const float* srcB0 = Y + (long long)bk0 * N + n0 + bn0 * 4;
    const float* srcB1 = srcB0 + (long long)8 * N;

    auto issue_tile = [&](int t) {
        const int stg = t % STAGES;
        const int k0  = t * BK;
        float* as = smem + stg * A_STAGE;
        float* bs = smem + B_BASE + stg * B_STAGE;
        CP_ASYNC16((uint32_t)__cvta_generic_to_shared(as + arow0 * A_PITCH + ac0 * 4), srcA0 + k0);
        CP_ASYNC16((uint32_t)__cvta_generic_to_shared(as + (arow0 + 64) * A_PITCH + ac0 * 4), srcA1 + k0);
        CP_ASYNC16((uint32_t)__cvta_generic_to_shared(bs + bk0 * B_PITCH + bn0 * 4),
                   srcB0 + (long long)k0 * N);
        CP_ASYNC16((uint32_t)__cvta_generic_to_shared(bs + (bk0 + 8) * B_PITCH + bn0 * 4),
                   srcB1 + (long long)k0 * N);
        CP_COMMIT();
    };

    float acc[2][8][4] = {};

    // ---- prologue: stages 0,1 in flight ----
    issue_tile(0);
    issue_tile(1);

    for (int t = 0; t < NS; ++t) {
        const int stg = t % STAGES;
        CP_WAIT1();             // tile t resident (only t+1 may be pending)
        __syncthreads();

        float* a_t = smem + stg * A_STAGE;
        float* b_t = smem + B_BASE + stg * B_STAGE;

        // identity subtraction on diagonal tiles (uniform branch per CTA)
        const int k0 = t * BK;
        if (k0 >= m0 && k0 < m0 + BM) {
            if (tid < BK) a_t[(k0 - m0 + tid) * A_PITCH + tid] -= 1.0f;
            __syncthreads();
        }

        if (t + 2 < NS) issue_tile(t + 2);

        #pragma unroll
        for (int kk = 0; kk < 2; kk++) {
            const int kb = kk * 8;
            uint32_t bfr[8][2], afr[2][4];
            #pragma unroll
            for (int nt = 0; nt < 8; nt++) {
                const float* bp = b_t + (kb + lq) * B_PITCH + warp_n * 64 + nt * 8 + lr;
                bfr[nt][0] = __float_as_uint(bp[0]);
                bfr[nt][1] = __float_as_uint(bp[4 * B_PITCH]);
            }
            #pragma unroll
            for (int mt = 0; mt < 2; mt++) {
                const float* ap = a_t + (warp_m * 32 + mt * 16 + lr) * A_PITCH + kb + lq;
                afr[mt][0] = __float_as_uint(ap[0]);
                afr[mt][1] = __float_as_uint(ap[8 * A_PITCH]);
                afr[mt][2] = __float_as_uint(ap[4]);
                afr[mt][3] = __float_as_uint(ap[8 * A_PITCH + 4]);
            }
            #pragma unroll
            for (int mt = 0; mt < 2; mt++)
                #pragma unroll
                for (int nt = 0; nt < 8; nt++)
                    MMA_TF32(acc[mt][nt], afr[mt], bfr[nt]);
        }
        __syncthreads();
    }

    // ---------------- fused epilogue ----------------
    const long long KN = (long long)Kd * N;
    const float kf  = (float)kptr[0];
    const float mom = (kf - 1.0f) / (kf + 2.0f);

    #pragma unroll
    for (int mt = 0; mt < 2; mt++) {
        #pragma unroll
        for (int i = 0; i < 2; i++) {
            const int row = m0 + warp_m * 32 + mt * 16 + lr + i * 8;
            #pragma unroll
            for (int nt = 0; nt < 8; nt++) {
                const int col = n0 + warp_n * 64 + nt * 8 + lq * 2;
                const long long gi = (long long)row * N + col;
                float2 y2  = *reinterpret_cast<const float2*>(&Y[gi]);
                float2 w2  = *reinterpret_cast<const float2*>(&W[gi]);
                float2 xo2 = *reinterpret_cast<const float2*>(&Xold[gi]);
                float d0 = acc[mt][nt][i * 2 + 0] + y2.x + w2.x;
                float d1 = acc[mt][nt][i * 2 + 1] + y2.y + w2.y;
                float nx0 = fmaxf(d0, 0.0f);
                float nx1 = fmaxf(d1, 0.0f);
                float2 yn, nx;
                nx.x = nx0; nx.y = nx1;
                yn.x = nx0 + mom * (nx0 - xo2.x);
                yn.y = nx1 + mom * (nx1 - xo2.y);
                *reinterpret_cast<float2*>(&out[gi])      = yn;  // Y_new
                *reinterpret_cast<float2*>(&out[KN + gi]) = nx;  // new_X
                out[2 * KN + 1 + gi]     = w2.x;                 // weight copy
                out[2 * KN + 1 + gi + 1] = w2.y;
            }
        }
    }
    if (m0 == 0 && n0 == 0 && tid == 0) out[2 * KN] = kf + 1.0f;
}

extern "C" void kernel_launch(void* const* d_in, const int* in_sizes, int n_in,
                              void* d_out, int out_size)
{
    const float* th1  = (const float*)d_in[0];
    const float* Y    = (const float*)d_in[1];
    const float* Xold = (const float*)d_in[2];
    const int*   kptr = (const int*)  d_in[3];
    const float* W    = (const float*)d_in[4];
    float* out = (float*)d_out;

    int Kd = (int)lround(sqrt((double)in_sizes[0]));
    int N  = in_sizes[1] / Kd;

    static int smem_set = 0;
    if (!smem_set) {
        cudaFuncSetAttribute(nnls_mma_kernel,
                             cudaFuncAttributeMaxDynamicSharedMemorySize, SMEM_BYTES);
        smem_set = 1;
    }

    dim3 grid(Kd / BM, N / BN);   // (8, 64)
    nnls_mma_kernel<<<grid, THREADS, SMEM_BYTES>>>(th1, Y, Xold, kptr, W, out, Kd, N);
}